// round 6
// baseline (speedup 1.0000x reference)
#include <cuda_runtime.h>
#include <cstdint>

#define N_RES 8192
#define N_IN  256
#define BATCH 16
#define NREP_H 8                 // histogram / cursor replicas
#define MAX_NNZ_RES 6720000      // actual: 6,710,886

// ---- device scratch ----
__device__ __align__(256) float g_ZT[N_RES * BATCH];   // bias + input-matrix part, [row][b]
__device__ __align__(256) float g_ST[N_RES * BATCH];   // state^T, [col][b]
__device__ __align__(256) float g_XT[N_IN * BATCH];    // x^T, [col][b]
__device__ int  g_counts[NREP_H][N_RES];
__device__ int  g_cursor[NREP_H][N_RES];
__device__ int  g_base[N_RES + 1];
__device__ unsigned long long g_csr[MAX_NNZ_RES];      // packed (col<<32 | val_bits)

__device__ __forceinline__ void red_add_v4(float* addr, float a, float b, float c, float d) {
    asm volatile("red.global.add.v4.f32 [%0], {%1, %2, %3, %4};"
                 :: "l"(addr), "f"(a), "f"(b), "f"(c), "f"(d)
                 : "memory");
}

// 1) transpose state->ST, x->XT, ZT=bias, zero hist replicas
__global__ void prep_kernel(const float* __restrict__ state,
                            const float* __restrict__ x,
                            const float* __restrict__ bias) {
    int t = blockIdx.x * blockDim.x + threadIdx.x;
    if (t < N_RES * BATCH) {
        int b = t >> 13;
        int r = t & (N_RES - 1);
        g_ST[r * BATCH + b] = state[t];
        g_ZT[r * BATCH + b] = bias[r];
    }
    if (t < N_IN * BATCH) {
        int b = t >> 8;
        int c = t & (N_IN - 1);
        g_XT[c * BATCH + b] = x[t];
    }
    if (t < NREP_H * N_RES) ((int*)g_counts)[t] = 0;
}

// 2) replicated row histogram
__global__ void hist_kernel(const int* __restrict__ rows, int nnz) {
    int i = blockIdx.x * blockDim.x + threadIdx.x;
    if (i >= nnz) return;
    int rep = (i >> 5) & (NREP_H - 1);
    atomicAdd(&g_counts[rep][rows[i]], 1);
}

// 3) exclusive scan over rows; per-(rep,row) cursor bases
__global__ void scan_kernel() {
    __shared__ int warpsum[32];
    int tid  = threadIdx.x;
    int lane = tid & 31;
    int w    = tid >> 5;

    int totals[8];
    int tsum = 0;
#pragma unroll
    for (int k = 0; k < 8; k++) {
        int row = tid * 8 + k;
        int s = 0;
#pragma unroll
        for (int rep = 0; rep < NREP_H; rep++) s += g_counts[rep][row];
        totals[k] = s;
        tsum += s;
    }

    int ss = tsum;
#pragma unroll
    for (int o = 1; o < 32; o <<= 1) {
        int n = __shfl_up_sync(0xffffffffu, ss, o);
        if (lane >= o) ss += n;
    }
    if (lane == 31) warpsum[w] = ss;
    __syncthreads();
    if (w == 0) {
        int t = warpsum[lane];
#pragma unroll
        for (int o = 1; o < 32; o <<= 1) {
            int n = __shfl_up_sync(0xffffffffu, t, o);
            if (lane >= o) t += n;
        }
        warpsum[lane] = t;
    }
    __syncthreads();

    int run = (w > 0 ? warpsum[w - 1] : 0) + ss - tsum;  // exclusive prefix
#pragma unroll
    for (int k = 0; k < 8; k++) {
        int row = tid * 8 + k;
        g_base[row] = run;
        int c = run;
#pragma unroll
        for (int rep = 0; rep < NREP_H; rep++) {
            g_cursor[rep][row] = c;
            c += g_counts[rep][row];
        }
        run += totals[k];
    }
    if (tid == 1023) g_base[N_RES] = run;
}

// 4) scatter COO -> row-sorted packed entries
__global__ void scatter_kernel(const float* __restrict__ vals,
                               const int*   __restrict__ rows,
                               const int*   __restrict__ cols, int nnz) {
    int i = blockIdx.x * blockDim.x + threadIdx.x;
    if (i >= nnz) return;
    int rep = (i >> 5) & (NREP_H - 1);
    int   row = rows[i];
    int   col = cols[i];
    float val = vals[i];
    int pos = atomicAdd(&g_cursor[rep][row], 1);
    g_csr[pos] = ((unsigned long long)(unsigned)col << 32) | (unsigned)__float_as_uint(val);
}

// 5) small input-matrix contribution: red into bias-initialized ZT
__global__ void in_spmm_kernel(const float* __restrict__ vals,
                               const int*   __restrict__ rows,
                               const int*   __restrict__ cols, int nnz) {
    int i = blockIdx.x * blockDim.x + threadIdx.x;
    if (i >= nnz) return;
    float val = vals[i];
    int   row = rows[i];
    int   col = cols[i];
    const float4* src = reinterpret_cast<const float4*>(g_XT) + col * 4;
    float4 s0 = src[0], s1 = src[1], s2 = src[2], s3 = src[3];
    float* dst = g_ZT + row * BATCH;
    red_add_v4(dst +  0, val * s0.x, val * s0.y, val * s0.z, val * s0.w);
    red_add_v4(dst +  4, val * s1.x, val * s1.y, val * s1.z, val * s1.w);
    red_add_v4(dst +  8, val * s2.x, val * s2.y, val * s2.z, val * s2.w);
    red_add_v4(dst + 12, val * s3.x, val * s3.y, val * s3.z, val * s3.w);
}

// 6) warp-per-row CSR SpMM, register accumulators, butterfly reduce, fused erf+transpose
__global__ void csr_spmm_kernel(float* __restrict__ out) {
    int warp_id = (blockIdx.x * blockDim.x + threadIdx.x) >> 5;
    int lane    = threadIdx.x & 31;
    if (warp_id >= N_RES) return;
    int row   = warp_id;
    int start = g_base[row];
    int end   = g_base[row + 1];

    float acc[16];
#pragma unroll
    for (int k = 0; k < 16; k++) acc[k] = 0.0f;

    for (int j = start + lane; j < end; j += 32) {
        unsigned long long e = g_csr[j];
        float val = __uint_as_float((unsigned)e);
        int   col = (int)(e >> 32);
        const float4* src = reinterpret_cast<const float4*>(g_ST) + col * 4;
        float4 s0 = __ldg(src + 0), s1 = __ldg(src + 1);
        float4 s2 = __ldg(src + 2), s3 = __ldg(src + 3);
        acc[0]  += val * s0.x;  acc[1]  += val * s0.y;
        acc[2]  += val * s0.z;  acc[3]  += val * s0.w;
        acc[4]  += val * s1.x;  acc[5]  += val * s1.y;
        acc[6]  += val * s1.z;  acc[7]  += val * s1.w;
        acc[8]  += val * s2.x;  acc[9]  += val * s2.y;
        acc[10] += val * s2.z;  acc[11] += val * s2.w;
        acc[12] += val * s3.x;  acc[13] += val * s3.y;
        acc[14] += val * s3.z;  acc[15] += val * s3.w;
    }

#pragma unroll
    for (int k = 0; k < 16; k++) {
#pragma unroll
        for (int o = 16; o > 0; o >>= 1)
            acc[k] += __shfl_xor_sync(0xffffffffu, acc[k], o);
    }

    if (lane < 16) {
        float z = acc[lane] + g_ZT[row * BATCH + lane];
        out[lane * N_RES + row] = erff(z);
    }
}

extern "C" void kernel_launch(void* const* d_in, const int* in_sizes, int n_in,
                              void* d_out, int out_size) {
    const float* state    = (const float*)d_in[0];
    const float* x        = (const float*)d_in[1];
    const float* res_vals = (const float*)d_in[2];
    const int*   res_rows = (const int*)  d_in[3];
    const int*   res_cols = (const int*)  d_in[4];
    const float* res_bias = (const float*)d_in[5];
    const float* in_vals  = (const float*)d_in[6];
    const int*   in_rows  = (const int*)  d_in[7];
    const int*   in_cols  = (const int*)  d_in[8];
    float* out = (float*)d_out;

    int nnz_res = in_sizes[2];
    int nnz_in  = in_sizes[6];

    const int TPB = 256;

    prep_kernel<<<(N_RES * BATCH + TPB - 1) / TPB, TPB>>>(state, x, res_bias);
    hist_kernel<<<(nnz_res + TPB - 1) / TPB, TPB>>>(res_rows, nnz_res);
    scan_kernel<<<1, 1024>>>();
    scatter_kernel<<<(nnz_res + TPB - 1) / TPB, TPB>>>(res_vals, res_rows, res_cols, nnz_res);
    in_spmm_kernel<<<(nnz_in + TPB - 1) / TPB, TPB>>>(in_vals, in_rows, in_cols, nnz_in);
    csr_spmm_kernel<<<(N_RES * 32 + TPB - 1) / TPB, TPB>>>(out);
}

// round 7
// speedup vs baseline: 2.6190x; 2.6190x over previous
#include <cuda_runtime.h>
#include <cstdint>

#define N_RES 8192
#define N_IN  256
#define BATCH 16
#define NREP  16          // accumulator replicas

// Scratch (device globals — runtime allocation prohibited)
__device__ __align__(256) float g_ZTR[NREP][N_RES * BATCH]; // replicated accumulators [rep][row][b]
__device__ __align__(256) float g_ST[N_RES * BATCH];        // state^T, [col][b]
__device__ __align__(256) float g_XT[N_IN * BATCH];         // x^T, [col][b]

__device__ __forceinline__ void red_add_v4(float* addr, float a, float b, float c, float d) {
    asm volatile("red.global.add.v4.f32 [%0], {%1, %2, %3, %4};"
                 :: "l"(addr), "f"(a), "f"(b), "f"(c), "f"(d)
                 : "memory");
}

// 1) transpose state -> ST, x -> XT
__global__ void prep_transpose_kernel(const float* __restrict__ state,
                                      const float* __restrict__ x) {
    int t = blockIdx.x * blockDim.x + threadIdx.x;
    if (t < N_RES * BATCH) {
        int b = t >> 13;
        int r = t & (N_RES - 1);
        g_ST[r * BATCH + b] = state[t];
    }
    if (t < N_IN * BATCH) {
        int b = t >> 8;
        int c = t & (N_IN - 1);
        g_XT[c * BATCH + b] = x[t];
    }
}

// 2) zero replicas (grid-stride, vectorized)
__global__ void prep_zero_kernel() {
    int t = blockIdx.x * blockDim.x + threadIdx.x;
    float4* z = reinterpret_cast<float4*>(&g_ZTR[0][0]);
    int total4 = NREP * N_RES * BATCH / 4;
    for (int i = t; i < total4; i += gridDim.x * blockDim.x)
        z[i] = make_float4(0.f, 0.f, 0.f, 0.f);
}

// 3) input-matrix contribution: 4 lanes per nnz (lane quarter q owns batch [4q,4q+4))
__global__ void in_spmm_kernel(const float* __restrict__ vals,
                               const int*   __restrict__ rows,
                               const int*   __restrict__ cols, int nnz) {
    int t = blockIdx.x * blockDim.x + threadIdx.x;
    int i = t >> 2;
    int q = t & 3;
    if (i >= nnz) return;
    int rep = (t >> 5) & (NREP - 1);

    float val = vals[i];
    int   row = rows[i];
    int   col = cols[i];

    float4 s = reinterpret_cast<const float4*>(g_XT)[col * 4 + q];
    float* dst = &g_ZTR[rep][row * BATCH + q * 4];
    red_add_v4(dst, val * s.x, val * s.y, val * s.z, val * s.w);
}

// 4) reservoir SpMM: 4 lanes per nnz — warp-coherent 16B gathers, one red.v4 per lane
__global__ void spmm_kernel(const float* __restrict__ vals,
                            const int*   __restrict__ rows,
                            const int*   __restrict__ cols, int nnz) {
    int t = blockIdx.x * blockDim.x + threadIdx.x;
    int i = t >> 2;            // nnz index (8 nnz per warp)
    int q = t & 3;             // batch quarter
    if (i >= nnz) return;
    int rep = (t >> 5) & (NREP - 1);   // per-warp replica

    float val = vals[i];       // 4-way redundant, sector-coalesced
    int   row = rows[i];
    int   col = cols[i];

    float4 s = reinterpret_cast<const float4*>(g_ST)[col * 4 + q];
    float* dst = &g_ZTR[rep][row * BATCH + q * 4];
    red_add_v4(dst, val * s.x, val * s.y, val * s.z, val * s.w);
}

// 5) reduce replicas + bias, erf, transposed write
__global__ void finish_kernel(const float* __restrict__ bias,
                              float* __restrict__ out) {
    int t = blockIdx.x * blockDim.x + threadIdx.x;
    if (t >= N_RES * BATCH) return;
    int r = t >> 4;
    int b = t & (BATCH - 1);

    float z = bias[r];
#pragma unroll
    for (int rep = 0; rep < NREP; rep++)
        z += g_ZTR[rep][t];
    out[b * N_RES + r] = erff(z);
}

extern "C" void kernel_launch(void* const* d_in, const int* in_sizes, int n_in,
                              void* d_out, int out_size) {
    const float* state    = (const float*)d_in[0];
    const float* x        = (const float*)d_in[1];
    const float* res_vals = (const float*)d_in[2];
    const int*   res_rows = (const int*)  d_in[3];
    const int*   res_cols = (const int*)  d_in[4];
    const float* res_bias = (const float*)d_in[5];
    const float* in_vals  = (const float*)d_in[6];
    const int*   in_rows  = (const int*)  d_in[7];
    const int*   in_cols  = (const int*)  d_in[8];
    float* out = (float*)d_out;

    int nnz_res = in_sizes[2];
    int nnz_in  = in_sizes[6];

    const int TPB = 256;

    prep_transpose_kernel<<<(N_RES * BATCH + TPB - 1) / TPB, TPB>>>(state, x);
    prep_zero_kernel<<<1024, TPB>>>();
    // 4 threads per nnz
    long long thr_in  = (long long)nnz_in * 4;
    in_spmm_kernel<<<(int)((thr_in + TPB - 1) / TPB), TPB>>>(in_vals, in_rows, in_cols, nnz_in);
    long long thr_res = (long long)nnz_res * 4;
    spmm_kernel<<<(int)((thr_res + TPB - 1) / TPB), TPB>>>(res_vals, res_rows, res_cols, nnz_res);
    finish_kernel<<<(N_RES * BATCH + TPB - 1) / TPB, TPB>>>(res_bias, out);
}

// round 8
// speedup vs baseline: 2.7097x; 1.0346x over previous
#include <cuda_runtime.h>
#include <cstdint>

#define N_RES 8192
#define N_IN  256
#define BATCH 16
#define NREP  16          // accumulator replicas

// Scratch (device globals — runtime allocation prohibited)
__device__ __align__(256) float g_ZTR[NREP][N_RES * BATCH]; // replicated accumulators [rep][row][b]
__device__ __align__(256) float g_ST[N_RES * BATCH];        // state^T, [col][b]
__device__ __align__(256) float g_XT[N_IN * BATCH];         // x^T, [col][b]

__device__ __forceinline__ void red_add_v4(float* addr, float a, float b, float c, float d) {
    asm volatile("red.global.add.v4.f32 [%0], {%1, %2, %3, %4};"
                 :: "l"(addr), "f"(a), "f"(b), "f"(c), "f"(d)
                 : "memory");
}

// 1) prep: transpose state -> ST, x -> XT, zero replicas (grid-stride)
__global__ void prep_kernel(const float* __restrict__ state,
                            const float* __restrict__ x) {
    int t = blockIdx.x * blockDim.x + threadIdx.x;
    if (t < N_RES * BATCH) {
        int b = t >> 13;
        int r = t & (N_RES - 1);
        g_ST[r * BATCH + b] = state[t];
    }
    if (t < N_IN * BATCH) {
        int b = t >> 8;
        int c = t & (N_IN - 1);
        g_XT[c * BATCH + b] = x[t];
    }
    float4* z = reinterpret_cast<float4*>(&g_ZTR[0][0]);
    int total4 = NREP * N_RES * BATCH / 4;
    for (int i = t; i < total4; i += gridDim.x * blockDim.x)
        z[i] = make_float4(0.f, 0.f, 0.f, 0.f);
}

// 2) combined SpMM: first in_blocks handle the input matrix (gather from XT),
//    remaining blocks handle the reservoir matrix (gather from ST).
//    4 lanes per nnz: lane quarter q owns batch slice [4q, 4q+4).
__global__ void spmm_all_kernel(const float* __restrict__ res_vals,
                                const int*   __restrict__ res_rows,
                                const int*   __restrict__ res_cols, int nnz_res,
                                const float* __restrict__ in_vals,
                                const int*   __restrict__ in_rows,
                                const int*   __restrict__ in_cols, int nnz_in,
                                int in_blocks) {
    const float* vals;
    const int*   rows;
    const int*   cols;
    const float* src_mat;
    int nnz, t;

    if (blockIdx.x < in_blocks) {
        vals = in_vals; rows = in_rows; cols = in_cols;
        src_mat = g_XT; nnz = nnz_in;
        t = blockIdx.x * blockDim.x + threadIdx.x;
    } else {
        vals = res_vals; rows = res_rows; cols = res_cols;
        src_mat = g_ST; nnz = nnz_res;
        t = (blockIdx.x - in_blocks) * blockDim.x + threadIdx.x;
    }

    int i = t >> 2;            // nnz index (8 nnz per warp)
    int q = t & 3;             // batch quarter
    if (i >= nnz) return;
    int rep = (t >> 5) & (NREP - 1);

    float val = vals[i];       // quartet-redundant, sector-coalesced
    int   row = rows[i];
    int   col = cols[i];

    float4 s = __ldg(reinterpret_cast<const float4*>(src_mat) + col * 4 + q);
    float* dst = &g_ZTR[rep][row * BATCH + q * 4];
    red_add_v4(dst, val * s.x, val * s.y, val * s.z, val * s.w);
}

// 3) reduce replicas + bias, erf, transposed write
__global__ void finish_kernel(const float* __restrict__ bias,
                              float* __restrict__ out) {
    int t = blockIdx.x * blockDim.x + threadIdx.x;
    if (t >= N_RES * BATCH) return;
    int r = t >> 4;
    int b = t & (BATCH - 1);

    float z = bias[r];
#pragma unroll
    for (int rep = 0; rep < NREP; rep++)
        z += g_ZTR[rep][t];
    out[b * N_RES + r] = erff(z);
}

extern "C" void kernel_launch(void* const* d_in, const int* in_sizes, int n_in,
                              void* d_out, int out_size) {
    const float* state    = (const float*)d_in[0];
    const float* x        = (const float*)d_in[1];
    const float* res_vals = (const float*)d_in[2];
    const int*   res_rows = (const int*)  d_in[3];
    const int*   res_cols = (const int*)  d_in[4];
    const float* res_bias = (const float*)d_in[5];
    const float* in_vals  = (const float*)d_in[6];
    const int*   in_rows  = (const int*)  d_in[7];
    const int*   in_cols  = (const int*)  d_in[8];
    float* out = (float*)d_out;

    int nnz_res = in_sizes[2];
    int nnz_in  = in_sizes[6];

    const int TPB = 256;

    prep_kernel<<<2048, TPB>>>(state, x);

    int in_blocks  = (int)(((long long)nnz_in  * 4 + TPB - 1) / TPB);
    int res_blocks = (int)(((long long)nnz_res * 4 + TPB - 1) / TPB);
    spmm_all_kernel<<<in_blocks + res_blocks, TPB>>>(
        res_vals, res_rows, res_cols, nnz_res,
        in_vals, in_rows, in_cols, nnz_in, in_blocks);

    finish_kernel<<<(N_RES * BATCH + TPB - 1) / TPB, TPB>>>(res_bias, out);
}